// round 3
// baseline (speedup 1.0000x reference)
#include <cuda_runtime.h>
#include <cuda_bf16.h>
#include <cstdint>

// Problem constants
#define DIM_D 1024
#define DIM_T 512
#define DIM_B 16384

// Tiling
#define BM 64
#define BN 512
#define BK 16
#define NTHREADS 512

#define AS_STRIDE 20   // 16 + pad, per-row floats in A stage
#define BS_STRIDE 520  // 512 + 8 pad (8 mod 32 -> conflict-free frag reads)

// smem layout (floats):
//   union region:
//     As[2][BM*AS_STRIDE]   = 2*64*20   = 2560
//     Bs[2][BK*BS_STRIDE]   = 2*16*520  = 16640   (total stage = 19200 floats)
//     S  [BM][BS_STRIDE]    = 64*520    = 33280   (epilogue, reuses region)
//   bhs[512]
//   Sbase[64*4]
#define SMEM_UNION_FLOATS 33280
#define SMEM_TOTAL_FLOATS (SMEM_UNION_FLOATS + 512 + 256)
#define SMEM_BYTES (SMEM_TOTAL_FLOATS * 4)

__device__ __forceinline__ float f2tf(float f) {
    unsigned u;
    asm("cvt.rna.tf32.f32 %0, %1;" : "=r"(u) : "f"(f));
    return __uint_as_float(u);
}

__device__ __forceinline__ void mma_tf32(float* c, const unsigned* a, const unsigned* b) {
    asm volatile(
        "mma.sync.aligned.m16n8k8.row.col.f32.tf32.tf32.f32 "
        "{%0,%1,%2,%3},{%4,%5,%6,%7},{%8,%9},{%0,%1,%2,%3};"
        : "+f"(c[0]), "+f"(c[1]), "+f"(c[2]), "+f"(c[3])
        : "r"(a[0]), "r"(a[1]), "r"(a[2]), "r"(a[3]), "r"(b[0]), "r"(b[1]));
}

__global__ __launch_bounds__(NTHREADS, 1)
void surv_kernel(const float* __restrict__ x,
                 const float* __restrict__ Wh,
                 const float* __restrict__ bh,
                 const float* __restrict__ Wb,
                 const float* __restrict__ bb,
                 float* __restrict__ out) {
    extern __shared__ float smem[];
    float* As = smem;                       // [2][BM*AS_STRIDE]
    float* Bs = smem + 2 * BM * AS_STRIDE;  // [2][BK*BS_STRIDE]
    float* S  = smem;                       // epilogue alias
    float* bhs   = smem + SMEM_UNION_FLOATS;
    float* Sbase = bhs + 512;

    const int tid  = threadIdx.x;
    const int warp = tid >> 5;
    const int lane = tid & 31;
    const int g    = lane >> 2;   // group 0..7
    const int tig  = lane & 3;    // thread-in-group 0..3
    const int wm   = warp & 1;    // 0..1  (M dimension, 32 rows each)
    const int wn   = warp >> 1;   // 0..7  (N dimension, 64 cols each)

    // bias into smem (512 threads, 512 values)
    bhs[tid] = bh[tid];

    // --- global load addressing ---
    // A: tid<256, arow = tid/4 (0..63), as_ = tid%4 -> 16B chunk of a 64B row segment
    const int arow = tid >> 2;
    const int as_  = tid & 3;
    const float* gA = x + (size_t)(blockIdx.x * BM + arow) * DIM_D + 4 * as_;
    // B: bt0 = tid%128, bs_ = tid/128 (0..3); each thread loads 4 rows of Wh (16B each)
    const int bt0 = tid & 127;
    const int bs_ = tid >> 7;
    const float* gB = Wh + (size_t)bt0 * DIM_D + 4 * bs_;

    float acc[2][8][4];
#pragma unroll
    for (int mt = 0; mt < 2; mt++)
#pragma unroll
        for (int nt = 0; nt < 8; nt++)
#pragma unroll
            for (int i = 0; i < 4; i++) acc[mt][nt][i] = 0.f;

    float4 ra;
    float4 rb[4];
    float base_part = 0.f;

    // ---- stage 0 load ----
    {
        const int k0 = 0;
        if (tid < 256) {
            ra = *reinterpret_cast<const float4*>(gA + k0);
            float4 wv = __ldg(reinterpret_cast<const float4*>(Wb + k0 + 4 * as_));
            base_part += ra.x * wv.x + ra.y * wv.y + ra.z * wv.z + ra.w * wv.w;
        }
#pragma unroll
        for (int i = 0; i < 4; i++)
            rb[i] = *reinterpret_cast<const float4*>(gB + (size_t)(i * 128) * DIM_D + k0);
    }
    // store stage 0 to buf 0
    {
        if (tid < 256) {
            float* a = As + arow * AS_STRIDE + 4 * as_;
            a[0] = f2tf(ra.x); a[1] = f2tf(ra.y); a[2] = f2tf(ra.z); a[3] = f2tf(ra.w);
        }
#pragma unroll
        for (int i = 0; i < 4; i++) {
            float* bsp = Bs + (4 * bs_) * BS_STRIDE + bt0 + 128 * i;
            bsp[0 * BS_STRIDE] = f2tf(rb[i].x);
            bsp[1 * BS_STRIDE] = f2tf(rb[i].y);
            bsp[2 * BS_STRIDE] = f2tf(rb[i].z);
            bsp[3 * BS_STRIDE] = f2tf(rb[i].w);
        }
    }
    __syncthreads();

    int buf = 0;
    const int NSTAGES = DIM_D / BK;  // 64
    for (int s = 0; s < NSTAGES; s++) {
        // prefetch next stage into regs
        if (s < NSTAGES - 1) {
            const int k0 = (s + 1) * BK;
            if (tid < 256) {
                ra = *reinterpret_cast<const float4*>(gA + k0);
                float4 wv = __ldg(reinterpret_cast<const float4*>(Wb + k0 + 4 * as_));
                base_part += ra.x * wv.x + ra.y * wv.y + ra.z * wv.z + ra.w * wv.w;
            }
#pragma unroll
            for (int i = 0; i < 4; i++)
                rb[i] = *reinterpret_cast<const float4*>(gB + (size_t)(i * 128) * DIM_D + k0);
        }

        // compute current buffer
        const float* Ab0 = As + buf * (BM * AS_STRIDE) + (wm * 32) * AS_STRIDE;
        const float* Bb0 = Bs + buf * (BK * BS_STRIDE) + wn * 64;
#pragma unroll
        for (int k8 = 0; k8 < 2; k8++) {
            const float* Ab = Ab0 + k8 * 8;
            const float* Bb = Bb0 + (k8 * 8) * BS_STRIDE;
            unsigned afr[2][4];
#pragma unroll
            for (int mt = 0; mt < 2; mt++) {
                const float* ar = Ab + (mt * 16 + g) * AS_STRIDE;
                afr[mt][0] = __float_as_uint(ar[tig]);
                afr[mt][1] = __float_as_uint(ar[8 * AS_STRIDE + tig]);
                afr[mt][2] = __float_as_uint(ar[tig + 4]);
                afr[mt][3] = __float_as_uint(ar[8 * AS_STRIDE + tig + 4]);
            }
            unsigned bfr[8][2];
#pragma unroll
            for (int nt = 0; nt < 8; nt++) {
                bfr[nt][0] = __float_as_uint(Bb[tig * BS_STRIDE + nt * 8 + g]);
                bfr[nt][1] = __float_as_uint(Bb[(tig + 4) * BS_STRIDE + nt * 8 + g]);
            }
#pragma unroll
            for (int mt = 0; mt < 2; mt++)
#pragma unroll
                for (int nt = 0; nt < 8; nt++)
                    mma_tf32(acc[mt][nt], afr[mt], bfr[nt]);
        }

        // store prefetched stage to other buffer
        if (s < NSTAGES - 1) {
            const int ob = buf ^ 1;
            if (tid < 256) {
                float* a = As + ob * (BM * AS_STRIDE) + arow * AS_STRIDE + 4 * as_;
                a[0] = f2tf(ra.x); a[1] = f2tf(ra.y); a[2] = f2tf(ra.z); a[3] = f2tf(ra.w);
            }
#pragma unroll
            for (int i = 0; i < 4; i++) {
                float* bsp = Bs + ob * (BK * BS_STRIDE) + (4 * bs_) * BS_STRIDE + bt0 + 128 * i;
                bsp[0 * BS_STRIDE] = f2tf(rb[i].x);
                bsp[1 * BS_STRIDE] = f2tf(rb[i].y);
                bsp[2 * BS_STRIDE] = f2tf(rb[i].z);
                bsp[3 * BS_STRIDE] = f2tf(rb[i].w);
            }
        }
        buf ^= 1;
        __syncthreads();
    }

    // ---- epilogue: relu + bias into smem S (reuses stage buffers) ----
#pragma unroll
    for (int mt = 0; mt < 2; mt++) {
#pragma unroll
        for (int nt = 0; nt < 8; nt++) {
            const int r = wm * 32 + mt * 16 + g;
            const int c = wn * 64 + nt * 8 + tig * 2;
            const float b0 = bhs[c], b1 = bhs[c + 1];
            S[r * BS_STRIDE + c]           = fmaxf(acc[mt][nt][0] + b0, 0.f);
            S[r * BS_STRIDE + c + 1]       = fmaxf(acc[mt][nt][1] + b1, 0.f);
            S[(r + 8) * BS_STRIDE + c]     = fmaxf(acc[mt][nt][2] + b0, 0.f);
            S[(r + 8) * BS_STRIDE + c + 1] = fmaxf(acc[mt][nt][3] + b1, 0.f);
        }
    }
    if (tid < 256) Sbase[arow * 4 + as_] = base_part;
    __syncthreads();

    // ---- cumsum per row: each warp handles 4 rows; segments of 32 with shfl scan ----
    const float bbv = __ldg(bb);
#pragma unroll
    for (int rr = 0; rr < 4; rr++) {
        const int r = warp * 4 + rr;
        const float base = bbv + Sbase[r * 4] + Sbase[r * 4 + 1] + Sbase[r * 4 + 2] + Sbase[r * 4 + 3];
        float run = base;
        float* out_row = out + (size_t)(blockIdx.x * BM + r) * DIM_T;
#pragma unroll
        for (int seg = 0; seg < 16; seg++) {
            float v = S[r * BS_STRIDE + seg * 32 + lane];
#pragma unroll
            for (int off = 1; off < 32; off <<= 1) {
                float t = __shfl_up_sync(0xffffffffu, v, off);
                if (lane >= off) v += t;
            }
            out_row[seg * 32 + lane] = run + v;
            run += __shfl_sync(0xffffffffu, v, 31);
        }
    }
}

extern "C" void kernel_launch(void* const* d_in, const int* in_sizes, int n_in,
                              void* d_out, int out_size) {
    const float* x  = (const float*)d_in[0];
    const float* Wh = (const float*)d_in[1];
    const float* bh = (const float*)d_in[2];
    const float* Wb = (const float*)d_in[3];
    const float* bb = (const float*)d_in[4];
    float* out = (float*)d_out;

    cudaFuncSetAttribute(surv_kernel, cudaFuncAttributeMaxDynamicSharedMemorySize, SMEM_BYTES);

    dim3 grid(DIM_B / BM);
    dim3 block(NTHREADS);
    surv_kernel<<<grid, block, SMEM_BYTES>>>(x, Wh, bh, Wb, bb, out);
}

// round 8
// speedup vs baseline: 1.9625x; 1.9625x over previous
#include <cuda_runtime.h>
#include <cstdint>

#define D_DIM 1024
#define T_DIM 512
#define BM    64
#define KC    32                 // k-floats per stage = 128 B rows
#define NSTAGES (D_DIM / KC)     // 32
#define NTHREADS 512
#define NBUF  3

// ---- smem layout (bytes) ----
#define SO_BH   0                // 512 floats
#define SO_WS   2048             // 8 x 64 floats (per-warp-col-block row sums)
#define SO_BASE 4096             // 64 floats
#define SO_A    4608             // 3 x 8192   (64 rows x 128B)
#define SO_B    29184            // 3 x 65536  (512 rows x 128B)
#define A_BUF   8192
#define B_BUF   65536
#define SMEM_BYTES 225792

__device__ __forceinline__ unsigned smem_u32(const void* p) {
    unsigned a;
    asm("{ .reg .u64 t; cvta.to.shared.u64 t, %1; cvt.u32.u64 %0, t; }" : "=r"(a) : "l"(p));
    return a;
}

__device__ __forceinline__ void cp16(unsigned dst, const void* src) {
    asm volatile("cp.async.cg.shared.global [%0], [%1], 16;" :: "r"(dst), "l"(src) : "memory");
}
#define CP_COMMIT() asm volatile("cp.async.commit_group;" ::: "memory")
#define CP_WAIT1()  asm volatile("cp.async.wait_group 1;" ::: "memory")

__device__ __forceinline__ void mma_tf32(float* c, const unsigned* a, const unsigned* b) {
    asm volatile(
        "mma.sync.aligned.m16n8k8.row.col.f32.tf32.tf32.f32 "
        "{%0,%1,%2,%3},{%4,%5,%6,%7},{%8,%9},{%0,%1,%2,%3};"
        : "+f"(c[0]), "+f"(c[1]), "+f"(c[2]), "+f"(c[3])
        : "r"(a[0]), "r"(a[1]), "r"(a[2]), "r"(a[3]), "r"(b[0]), "r"(b[1]));
}

__global__ __launch_bounds__(NTHREADS, 1)
void surv_k6(const float* __restrict__ x,
             const float* __restrict__ Wh,
             const float* __restrict__ bh,
             const float* __restrict__ Wb,
             const float* __restrict__ bb,
             float* __restrict__ out) {
    extern __shared__ char smem[];
    const unsigned sb = smem_u32(smem);
    float* bhs   = (float*)(smem + SO_BH);
    float* ws    = (float*)(smem + SO_WS);
    float* basef = (float*)(smem + SO_BASE);

    const int tid  = threadIdx.x;
    const int warp = tid >> 5;
    const int lane = tid & 31;
    const int g    = lane >> 2;
    const int tig  = lane & 3;
    const int wm   = warp & 1;      // M half (32 rows)
    const int wn   = warp >> 1;     // N block (64 cols)

    bhs[tid] = bh[tid];

    // ---- cp.async addressing ----
    // one 16B unit per (row, u): A 64x8 units (1/thread), B 512x8 units (8/thread)
    const int lrow = tid >> 3;      // 0..63
    const int lu   = tid & 7;       // 0..7
    const float* gA = x + (size_t)(blockIdx.x * BM + lrow) * D_DIM + lu * 4;
    const float* gB = Wh + (size_t)lrow * D_DIM + lu * 4;
    const unsigned aswz = (unsigned)((lu ^ (lrow & 7)) * 16);
    const unsigned adst0 = sb + SO_A + (unsigned)lrow * 128 + aswz;
    const unsigned bdst0 = sb + SO_B + (unsigned)lrow * 128 + aswz;

    auto load_stage = [&](int s, int buf) {
        const int k0 = s * KC;
        cp16(adst0 + buf * A_BUF, gA + k0);
        const unsigned bd = bdst0 + buf * B_BUF;
#pragma unroll
        for (int j = 0; j < 8; j++)
            cp16(bd + j * (64 * 128), gB + (size_t)j * 64 * D_DIM + k0);
    };

    float acc[2][8][4];
#pragma unroll
    for (int mt = 0; mt < 2; mt++)
#pragma unroll
        for (int nt = 0; nt < 8; nt++)
#pragma unroll
            for (int i = 0; i < 4; i++) acc[mt][nt][i] = 0.f;

    // ---- pipeline: distance-1 prefetch, 3 buffers, 1 sync/stage ----
    load_stage(0, 0);
    CP_COMMIT();

    // fragment base addresses (this warp)
    // A: row r = wm*32 + mt*16 + g (+8); swizzle key = g; u = kk*2 (+1)
    // B: row t = wn*64 + nt*8 + g;       swizzle key = g; u = kk*2 (+1)
    const unsigned afrag0 = sb + SO_A + (unsigned)(wm * 32 + g) * 128 + (unsigned)tig * 4;
    const unsigned bfrag0 = sb + SO_B + (unsigned)(wn * 64 + g) * 128 + (unsigned)tig * 4;

    for (int s = 0; s < NSTAGES; s++) {
        if (s + 1 < NSTAGES) load_stage(s + 1, (s + 1) % NBUF);
        CP_COMMIT();
        CP_WAIT1();
        __syncthreads();

        const int buf = s % NBUF;
        const unsigned ab = afrag0 + buf * A_BUF;
        const unsigned bbse = bfrag0 + buf * B_BUF;
#pragma unroll
        for (int kk = 0; kk < 4; kk++) {
            const unsigned u0 = (unsigned)(((kk * 2) ^ g) * 16);
            const unsigned u1 = (unsigned)(((kk * 2 + 1) ^ g) * 16);
            unsigned afr[2][4];
#pragma unroll
            for (int mt = 0; mt < 2; mt++) {
                const unsigned ar = ab + mt * (16 * 128);
                asm volatile("ld.shared.b32 %0, [%1];" : "=r"(afr[mt][0]) : "r"(ar + u0));
                asm volatile("ld.shared.b32 %0, [%1];" : "=r"(afr[mt][1]) : "r"(ar + u0 + 8 * 128));
                asm volatile("ld.shared.b32 %0, [%1];" : "=r"(afr[mt][2]) : "r"(ar + u1));
                asm volatile("ld.shared.b32 %0, [%1];" : "=r"(afr[mt][3]) : "r"(ar + u1 + 8 * 128));
            }
            unsigned bfr[8][2];
#pragma unroll
            for (int nt = 0; nt < 8; nt++) {
                const unsigned br = bbse + nt * (8 * 128);
                asm volatile("ld.shared.b32 %0, [%1];" : "=r"(bfr[nt][0]) : "r"(br + u0));
                asm volatile("ld.shared.b32 %0, [%1];" : "=r"(bfr[nt][1]) : "r"(br + u1));
            }
#pragma unroll
            for (int mt = 0; mt < 2; mt++)
#pragma unroll
                for (int nt = 0; nt < 8; nt++)
                    mma_tf32(acc[mt][nt], afr[mt], bfr[nt]);
        }
        // note: next iteration's load targets buf (s+2)%3 != (s)%3 and != (s+1)%3 readers —
        // the single barrier above provides the needed separation.
    }

    // ---- epilogue ----
    // 1) relu+bias, in-register inclusive scan within each 64-col warp block
    const unsigned fullm = 0xffffffffu;
#pragma unroll
    for (int mt = 0; mt < 2; mt++) {
#pragma unroll
        for (int h = 0; h < 2; h++) {
            float run = 0.f;
            const int rowlocal = wm * 32 + mt * 16 + g + h * 8;
#pragma unroll
            for (int nt = 0; nt < 8; nt++) {
                const int c = wn * 64 + nt * 8 + tig * 2;
                float v0 = fmaxf(acc[mt][nt][2 * h + 0] + bhs[c], 0.f);
                float v1 = fmaxf(acc[mt][nt][2 * h + 1] + bhs[c + 1], 0.f);
                float pair = v0 + v1;
                float incl = pair;
                float t = __shfl_up_sync(fullm, incl, 1, 4);
                if (tig >= 1) incl += t;
                t = __shfl_up_sync(fullm, incl, 2, 4);
                if (tig >= 2) incl += t;
                float excl = incl - pair;
                acc[mt][nt][2 * h + 0] = run + excl + v0;
                acc[mt][nt][2 * h + 1] = run + excl + pair;
                run += __shfl_sync(fullm, incl, 3, 4);
            }
            if (tig == 0) ws[wn * 64 + rowlocal] = run;
        }
    }

    // 2) base term: base[r] = bb + x[r,:]*Wb ; 8 threads per row, 128 floats each
    {
        const int r = tid >> 3;
        const int part = tid & 7;
        const float* xr = x + (size_t)(blockIdx.x * BM + r) * D_DIM + part * 128;
        const float* wr = Wb + part * 128;
        float p = 0.f;
#pragma unroll
        for (int i = 0; i < 32; i++) {
            float4 a = ((const float4*)xr)[i];
            float4 w = ((const float4*)wr)[i];
            p += a.x * w.x + a.y * w.y + a.z * w.z + a.w * w.w;
        }
        p += __shfl_xor_sync(fullm, p, 4, 8);
        p += __shfl_xor_sync(fullm, p, 2, 8);
        p += __shfl_xor_sync(fullm, p, 1, 8);
        if (part == 0) basef[r] = p + __ldg(bb);
    }
    __syncthreads();

    // 3) add cross-block offsets and store
#pragma unroll
    for (int mt = 0; mt < 2; mt++) {
#pragma unroll
        for (int h = 0; h < 2; h++) {
            const int rowlocal = wm * 32 + mt * 16 + g + h * 8;
            float off = basef[rowlocal];
            for (int j = 0; j < wn; j++) off += ws[j * 64 + rowlocal];
            float* orow = out + (size_t)(blockIdx.x * BM + rowlocal) * T_DIM;
#pragma unroll
            for (int nt = 0; nt < 8; nt++) {
                const int c = wn * 64 + nt * 8 + tig * 2;
                float2 v;
                v.x = off + acc[mt][nt][2 * h + 0];
                v.y = off + acc[mt][nt][2 * h + 1];
                *(float2*)(orow + c) = v;
            }
        }
    }
}

extern "C" void kernel_launch(void* const* d_in, const int* in_sizes, int n_in,
                              void* d_out, int out_size) {
    const float* x  = (const float*)d_in[0];
    const float* Wh = (const float*)d_in[1];
    const float* bh = (const float*)d_in[2];
    const float* Wb = (const float*)d_in[3];
    const float* bb = (const float*)d_in[4];
    float* out = (float*)d_out;

    cudaFuncSetAttribute(surv_k6, cudaFuncAttributeMaxDynamicSharedMemorySize, SMEM_BYTES);
    surv_k6<<<16384 / BM, NTHREADS, SMEM_BYTES>>>(x, Wh, bh, Wb, bb, out);
}

// round 9
// speedup vs baseline: 2.2145x; 1.1284x over previous
#include <cuda_runtime.h>
#include <cuda_fp16.h>
#include <cstdint>

#define D_DIM 1024
#define T_DIM 512
#define BM    64
#define KC    32                 // k-floats per stage (fp16 rows = 64 B)
#define NSTAGES 32
#define NTHREADS 512
#define NBUF  4

// ---- smem layout (bytes) ----
#define SO_BH   0                // 512 floats bias
#define SO_WS   2048             // 8 x 64 floats per-block row sums
#define SO_BASE 4096             // 64 floats
#define SO_A    4608             // 4 x 4096   (64 rows x 64B fp16)
#define SO_B    20992            // 4 x 32768  (512 rows x 64B fp16)
#define A_BUF   4096
#define B_BUF   32768
#define SMEM_BYTES 152064

__device__ __forceinline__ unsigned smem_u32(const void* p) {
    unsigned a;
    asm("{ .reg .u64 t; cvta.to.shared.u64 t, %1; cvt.u32.u64 %0, t; }" : "=r"(a) : "l"(p));
    return a;
}

// pack two fp32 -> f16x2 (round-nearest). PTX src0 -> high half, src1 -> low half.
__device__ __forceinline__ unsigned cvt2(float lo, float hi) {
    unsigned r;
    asm("cvt.rn.f16x2.f32 %0, %1, %2;" : "=r"(r) : "f"(hi), "f"(lo));
    return r;
}

__device__ __forceinline__ unsigned lds32(unsigned a) {
    unsigned v;
    asm volatile("ld.shared.b32 %0, [%1];" : "=r"(v) : "r"(a));
    return v;
}

__device__ __forceinline__ void mma_f16(float* c, const unsigned* a, const unsigned* b) {
    asm volatile(
        "mma.sync.aligned.m16n8k16.row.col.f32.f16.f16.f32 "
        "{%0,%1,%2,%3},{%4,%5,%6,%7},{%8,%9},{%0,%1,%2,%3};"
        : "+f"(c[0]), "+f"(c[1]), "+f"(c[2]), "+f"(c[3])
        : "r"(a[0]), "r"(a[1]), "r"(a[2]), "r"(a[3]), "r"(b[0]), "r"(b[1]));
}

__global__ __launch_bounds__(NTHREADS, 1)
void surv_k9(const float* __restrict__ x,
             const float* __restrict__ Wh,
             const float* __restrict__ bh,
             const float* __restrict__ Wb,
             const float* __restrict__ bb,
             float* __restrict__ out) {
    extern __shared__ char smem[];
    const unsigned sb = smem_u32(smem);
    float* bhs   = (float*)(smem + SO_BH);
    float* ws    = (float*)(smem + SO_WS);
    float* basef = (float*)(smem + SO_BASE);

    const int tid  = threadIdx.x;
    const int warp = tid >> 5;
    const int lane = tid & 31;
    const int g    = lane >> 2;
    const int tig  = lane & 3;
    const int wm   = warp & 1;      // M half (32 rows)
    const int wn   = warp >> 1;     // N block (64 cols)

    bhs[tid] = bh[tid];

    // ---- staging addressing: one thread handles 16B fp32 chunks ----
    const int srow = tid >> 3;      // 0..63
    const int sj   = tid & 7;       // which 4-float chunk of the 32-float stage row
    const float* gA = x + (size_t)(blockIdx.x * BM + srow) * D_DIM + sj * 4;
    const float* gB = Wh + (size_t)srow * D_DIM + sj * 4;
    unsigned stoA, stoB;
    {
        unsigned o = (unsigned)(srow * 64 + sj * 8);
        o ^= (o >> 3) & 0x30;       // SW64-style swizzle on 16B units
        stoA = SO_A + o;
        stoB = SO_B + o;            // +i*4096 per 64-row group (doesn't touch swz bits)
    }

    auto load_stage = [&](int s, int buf) {
        const int k0 = s * KC;
        {
            float4 v = *(const float4*)(gA + k0);
            uint2 h;
            h.x = cvt2(v.x, v.y);
            h.y = cvt2(v.z, v.w);
            *(uint2*)(smem + stoA + buf * A_BUF) = h;
        }
        char* bp = smem + stoB + buf * B_BUF;
#pragma unroll
        for (int i = 0; i < 8; i++) {
            float4 v = *(const float4*)(gB + (size_t)(i * 64) * D_DIM + k0);
            uint2 h;
            h.x = cvt2(v.x, v.y);
            h.y = cvt2(v.z, v.w);
            *(uint2*)(bp + i * 4096) = h;
        }
    };

    float acc[2][8][4];
#pragma unroll
    for (int mt = 0; mt < 2; mt++)
#pragma unroll
        for (int nt = 0; nt < 8; nt++)
#pragma unroll
            for (int i = 0; i < 4; i++) acc[mt][nt][i] = 0.f;

    // ---- fragment addressing ----
    const unsigned key = (unsigned)((g & 6) << 3);
    const unsigned C0 = key;        //  0 ^ key
    const unsigned C1 = 16u ^ key;
    const unsigned C2 = 32u ^ key;
    const unsigned C3 = 48u ^ key;
    const unsigned paw = sb + SO_A + (unsigned)((wm * 32 + g) * 64 + tig * 4);
    const unsigned pbw = sb + SO_B + (unsigned)((wn * 64 + g) * 64 + tig * 4);

    auto compute_stage = [&](int buf) {
        const unsigned ab = paw + buf * A_BUF;
        const unsigned bbs = pbw + buf * B_BUF;
#pragma unroll
        for (int kk = 0; kk < 2; kk++) {
            const unsigned cu0 = kk ? C2 : C0;
            const unsigned cu1 = kk ? C3 : C1;
            unsigned afr[2][4];
#pragma unroll
            for (int mt = 0; mt < 2; mt++) {
                const unsigned a0 = ab + mt * 1024;          // mt*16 rows * 64B
                afr[mt][0] = lds32(a0 + cu0);
                afr[mt][1] = lds32(a0 + 512 + cu0);          // +8 rows
                afr[mt][2] = lds32(a0 + cu1);
                afr[mt][3] = lds32(a0 + 512 + cu1);
            }
            unsigned bfr[8][2];
#pragma unroll
            for (int nt = 0; nt < 8; nt++) {
                const unsigned b0 = bbs + nt * 512;          // nt*8 rows * 64B
                bfr[nt][0] = lds32(b0 + cu0);
                bfr[nt][1] = lds32(b0 + cu1);
            }
#pragma unroll
            for (int mt = 0; mt < 2; mt++)
#pragma unroll
                for (int nt = 0; nt < 8; nt++)
                    mma_f16(acc[mt][nt], afr[mt], bfr[nt]);
        }
    };

    // ---- pipeline: NBUF=4, one barrier per 2 stages ----
    load_stage(0, 0);
    load_stage(1, 1);
    __syncthreads();

#pragma unroll 2
    for (int p = 0; p < NSTAGES / 2; p++) {
        const int s0 = 2 * p;
        if (s0 + 2 < NSTAGES) load_stage(s0 + 2, (s0 + 2) & 3);
        compute_stage(s0 & 3);
        if (s0 + 3 < NSTAGES) load_stage(s0 + 3, (s0 + 3) & 3);
        compute_stage((s0 + 1) & 3);
        __syncthreads();
    }

    // ---- epilogue ----
    const unsigned fullm = 0xffffffffu;
    // 1) relu+bias + in-register inclusive scan within each 64-col warp block
#pragma unroll
    for (int mt = 0; mt < 2; mt++) {
#pragma unroll
        for (int h = 0; h < 2; h++) {
            float run = 0.f;
            const int rowlocal = wm * 32 + mt * 16 + g + h * 8;
#pragma unroll
            for (int nt = 0; nt < 8; nt++) {
                const int c = wn * 64 + nt * 8 + tig * 2;
                float v0 = fmaxf(acc[mt][nt][2 * h + 0] + bhs[c], 0.f);
                float v1 = fmaxf(acc[mt][nt][2 * h + 1] + bhs[c + 1], 0.f);
                float pair = v0 + v1;
                float incl = pair;
                float t = __shfl_up_sync(fullm, incl, 1, 4);
                if (tig >= 1) incl += t;
                t = __shfl_up_sync(fullm, incl, 2, 4);
                if (tig >= 2) incl += t;
                float excl = incl - pair;
                acc[mt][nt][2 * h + 0] = run + excl + v0;
                acc[mt][nt][2 * h + 1] = run + excl + pair;
                run += __shfl_sync(fullm, incl, 3, 4);
            }
            if (tig == 0) ws[wn * 64 + rowlocal] = run;
        }
    }

    // 2) base term: base[r] = bb + x[r,:].Wb  (8 threads/row, fp32, exact-ish)
    {
        const int r = tid >> 3;
        const int part = tid & 7;
        const float* xr = x + (size_t)(blockIdx.x * BM + r) * D_DIM + part * 128;
        const float* wr = Wb + part * 128;
        float pdot = 0.f;
#pragma unroll
        for (int i = 0; i < 32; i++) {
            float4 a = ((const float4*)xr)[i];
            float4 w = ((const float4*)wr)[i];
            pdot += a.x * w.x + a.y * w.y + a.z * w.z + a.w * w.w;
        }
        pdot += __shfl_xor_sync(fullm, pdot, 4, 8);
        pdot += __shfl_xor_sync(fullm, pdot, 2, 8);
        pdot += __shfl_xor_sync(fullm, pdot, 1, 8);
        if (part == 0) basef[r] = pdot + __ldg(bb);
    }
    __syncthreads();

    // 3) add cross-block offsets and store
#pragma unroll
    for (int mt = 0; mt < 2; mt++) {
#pragma unroll
        for (int h = 0; h < 2; h++) {
            const int rowlocal = wm * 32 + mt * 16 + g + h * 8;
            float off = basef[rowlocal];
            for (int j = 0; j < wn; j++) off += ws[j * 64 + rowlocal];
            float* orow = out + (size_t)(blockIdx.x * BM + rowlocal) * T_DIM;
#pragma unroll
            for (int nt = 0; nt < 8; nt++) {
                const int c = wn * 64 + nt * 8 + tig * 2;
                float2 v;
                v.x = off + acc[mt][nt][2 * h + 0];
                v.y = off + acc[mt][nt][2 * h + 1];
                *(float2*)(orow + c) = v;
            }
        }
    }
}

extern "C" void kernel_launch(void* const* d_in, const int* in_sizes, int n_in,
                              void* d_out, int out_size) {
    const float* x  = (const float*)d_in[0];
    const float* Wh = (const float*)d_in[1];
    const float* bh = (const float*)d_in[2];
    const float* Wb = (const float*)d_in[3];
    const float* bb = (const float*)d_in[4];
    float* out = (float*)d_out;

    cudaFuncSetAttribute(surv_k9, cudaFuncAttributeMaxDynamicSharedMemorySize, SMEM_BYTES);
    surv_k9<<<16384 / BM, NTHREADS, SMEM_BYTES>>>(x, Wh, bh, Wb, bb, out);
}